// round 7
// baseline (speedup 1.0000x reference)
#include <cuda_runtime.h>
#include <cuda_bf16.h>
#include <math.h>

#define MAXN 100000
#define MAXE 1600000
#define HDIM 64

// ---------------- scratch (static device globals; no allocation) -------------
__device__ int    g_counts [MAXN];
__device__ int    g_offsets[MAXN];
__device__ int    g_cursor [MAXN];
__device__ float  g_dis    [MAXN];
__device__ float2 g_epack  [MAXE];        // .x = __int_as_float(src), .y = norm
__device__ float  g_agg    [MAXN * HDIM];
__device__ float  g_h      [MAXN * HDIM];
__device__ int    g_bsum   [512];
__device__ int    g_is64;   // 1 if edge_index buffer is int64, 0 if int32

// ---------------- zero + dtype probe -----------------------------------------
// True int64 indices read as int64 lie in [0, n). An int32 buffer misread as
// int64 packs two indices per word -> values >= 2^32. Deterministic.
__global__ void k_zero_probe(const void* __restrict__ ei_raw, int n) {
    int i = blockIdx.x * blockDim.x + threadIdx.x;
    if (i < n) g_counts[i] = 0;
    if (i == 0) {
        const long long* e64 = (const long long*)ei_raw;
        int ok64 = 1;
        for (int k = 0; k < 8; k++) {
            long long v = e64[k];
            if (v < 0 || v >= (long long)n) ok64 = 0;
        }
        g_is64 = ok64;
    }
}

// ---------------- count in-degrees (vectorized: 2 edges/thread) --------------
__global__ void k_count(const void* __restrict__ ei_raw, int e, int n) {
    int i = blockIdx.x * blockDim.x + threadIdx.x;   // pair index
    if (2 * i >= e) return;
    int d0, d1;
    if (g_is64) {
        const longlong2* p = (const longlong2*)((const long long*)ei_raw + e);
        longlong2 v = __ldg(&p[i]);
        d0 = (int)v.x; d1 = (int)v.y;
    } else {
        const int2* p = (const int2*)((const int*)ei_raw + e);
        int2 v = __ldg(&p[i]);
        d0 = v.x; d1 = v.y;
    }
    if ((unsigned)d0 < (unsigned)n) atomicAdd(&g_counts[d0], 1);
    if ((unsigned)d1 < (unsigned)n) atomicAdd(&g_counts[d1], 1);
}

// Block-level exclusive scan of counts (512/block); also dis = rsqrt(deg+1)
__global__ void k_scan1(int n) {
    __shared__ int s[512];
    int t = threadIdx.x;
    int i = blockIdx.x * 512 + t;
    int v = (i < n) ? g_counts[i] : 0;
    s[t] = v;
    __syncthreads();
#pragma unroll
    for (int off = 1; off < 512; off <<= 1) {
        int tv = (t >= off) ? s[t - off] : 0;
        __syncthreads();
        s[t] += tv;
        __syncthreads();
    }
    if (i < n) {
        g_offsets[i] = s[t] - v;
        g_dis[i]     = rsqrtf((float)(v + 1));
    }
    if (t == 511) g_bsum[blockIdx.x] = s[511];
}

__global__ void k_scan2(int nb) {
    __shared__ int s[512];
    int t = threadIdx.x;
    int v = (t < nb) ? g_bsum[t] : 0;
    s[t] = v;
    __syncthreads();
#pragma unroll
    for (int off = 1; off < 512; off <<= 1) {
        int tv = (t >= off) ? s[t - off] : 0;
        __syncthreads();
        s[t] += tv;
        __syncthreads();
    }
    if (t < nb) g_bsum[t] = s[t] - v;
}

__global__ void k_scan3(int n) {
    int i = blockIdx.x * 512 + threadIdx.x;
    if (i < n) {
        int o = g_offsets[i] + g_bsum[blockIdx.x];
        g_offsets[i] = o;
        g_cursor[i]  = o;
    }
}

// ---------------- fill CSR (vectorized: 2 edges/thread) ----------------------
__global__ void k_fill(const void* __restrict__ ei_raw, int e, int n) {
    int i = blockIdx.x * blockDim.x + threadIdx.x;   // pair index
    if (2 * i >= e) return;
    int s0, s1, d0, d1;
    if (g_is64) {
        const longlong2* ps = (const longlong2*)((const long long*)ei_raw);
        const longlong2* pd = (const longlong2*)((const long long*)ei_raw + e);
        longlong2 vs = __ldg(&ps[i]);
        longlong2 vd = __ldg(&pd[i]);
        s0 = (int)vs.x; s1 = (int)vs.y; d0 = (int)vd.x; d1 = (int)vd.y;
    } else {
        const int2* ps = (const int2*)((const int*)ei_raw);
        const int2* pd = (const int2*)((const int*)ei_raw + e);
        int2 vs = __ldg(&ps[i]);
        int2 vd = __ldg(&pd[i]);
        s0 = vs.x; s1 = vs.y; d0 = vd.x; d1 = vd.y;
    }
    if ((unsigned)s0 < (unsigned)n && (unsigned)d0 < (unsigned)n) {
        int p = atomicAdd(&g_cursor[d0], 1);
        g_epack[p] = make_float2(__int_as_float(s0), g_dis[s0] * g_dis[d0]);
    }
    if ((unsigned)s1 < (unsigned)n && (unsigned)d1 < (unsigned)n) {
        int p = atomicAdd(&g_cursor[d1], 1);
        g_epack[p] = make_float2(__int_as_float(s1), g_dis[s1] * g_dis[d1]);
    }
}

// ---------------- aggregation: g_agg = A_norm_with_selfloops * in ------------
// Warp per destination node, HALF-WARP PER EDGE: lanes 0-15 take even edges,
// lanes 16-31 odd edges; each lane covers 16B (float4) of the 256B row. One
// LDG.128 gather instruction serves 2 edges (same wavefronts, half the issue
// slots vs LDG.64-per-edge). Meta for 2 edges = one broadcast LDG.128 (pair
// start forced even for 16B alignment). Cross-half combine via 4 shfl_xor(16).
__global__ void k_agg(const float* __restrict__ xin, int n, int from_x) {
    int warp = (blockIdx.x * blockDim.x + threadIdx.x) >> 5;
    int lane = threadIdx.x & 31;
    if (warp >= n) return;

    const float4* __restrict__ in4 =
        (const float4*)(from_x ? xin : (const float*)g_h);

    const int half = lane >> 4;          // 0: even edges, 1: odd edges
    const int l16  = lane & 15;

    float di    = g_dis[warp];
    float selfc = di * di;

    float4 acc = make_float4(0.f, 0.f, 0.f, 0.f);
    if (half == 0) {                      // self-loop handled by half 0
        float4 r = __ldg(&in4[(size_t)warp * 16 + l16]);
        acc.x = r.x * selfc; acc.y = r.y * selfc;
        acc.z = r.z * selfc; acc.w = r.w * selfc;
    }

    int start = g_offsets[warp];
    int cnt   = g_counts[warp];

    // Align pair base to even index (16B) — head edge handled by half 0.
    if (cnt > 0 && (start & 1)) {
        if (half == 0) {
            float2 m = __ldg(&g_epack[start]);
            float4 v = __ldg(&in4[(size_t)__float_as_int(m.x) * 16 + l16]);
            acc.x = fmaf(m.y, v.x, acc.x); acc.y = fmaf(m.y, v.y, acc.y);
            acc.z = fmaf(m.y, v.z, acc.z); acc.w = fmaf(m.y, v.w, acc.w);
        }
        start++; cnt--;
    }

    const float4* __restrict__ mp = (const float4*)&g_epack[start]; // 16B aligned
    int pairs = cnt >> 1;
    int p = 0;
    for (; p + 2 <= pairs; p += 2) {      // 4 edges in flight
        float4 m0 = __ldg(mp + p);
        float4 m1 = __ldg(mp + p + 1);
        int   s0 = __float_as_int(half ? m0.z : m0.x);
        int   s1 = __float_as_int(half ? m1.z : m1.x);
        float w0 = half ? m0.w : m0.y;
        float w1 = half ? m1.w : m1.y;
        float4 v0 = __ldg(&in4[(size_t)s0 * 16 + l16]);
        float4 v1 = __ldg(&in4[(size_t)s1 * 16 + l16]);
        acc.x = fmaf(w0, v0.x, acc.x); acc.y = fmaf(w0, v0.y, acc.y);
        acc.z = fmaf(w0, v0.z, acc.z); acc.w = fmaf(w0, v0.w, acc.w);
        acc.x = fmaf(w1, v1.x, acc.x); acc.y = fmaf(w1, v1.y, acc.y);
        acc.z = fmaf(w1, v1.z, acc.z); acc.w = fmaf(w1, v1.w, acc.w);
    }
    for (; p < pairs; p++) {
        float4 m = __ldg(mp + p);
        int   s = __float_as_int(half ? m.z : m.x);
        float w = half ? m.w : m.y;
        float4 v = __ldg(&in4[(size_t)s * 16 + l16]);
        acc.x = fmaf(w, v.x, acc.x); acc.y = fmaf(w, v.y, acc.y);
        acc.z = fmaf(w, v.z, acc.z); acc.w = fmaf(w, v.w, acc.w);
    }
    if (cnt & 1) {                        // odd tail edge -> half 0
        if (half == 0) {
            float2 m = __ldg(&g_epack[start + cnt - 1]);
            float4 v = __ldg(&in4[(size_t)__float_as_int(m.x) * 16 + l16]);
            acc.x = fmaf(m.y, v.x, acc.x); acc.y = fmaf(m.y, v.y, acc.y);
            acc.z = fmaf(m.y, v.z, acc.z); acc.w = fmaf(m.y, v.w, acc.w);
        }
    }

    // combine halves (lane l <- lane l^16) and store from half 0
    acc.x += __shfl_xor_sync(0xffffffffu, acc.x, 16);
    acc.y += __shfl_xor_sync(0xffffffffu, acc.y, 16);
    acc.z += __shfl_xor_sync(0xffffffffu, acc.z, 16);
    acc.w += __shfl_xor_sync(0xffffffffu, acc.w, 16);
    if (half == 0)
        ((float4*)g_agg)[(size_t)warp * 16 + l16] = acc;
}

// ---------------- GEMM: out = [relu](g_agg @ W + b),  g_agg: n x 64 ----------
__global__ void k_gemm(const float* __restrict__ W, const float* __restrict__ b,
                       float* __restrict__ outp, int n, int do_relu, int to_out) {
    __shared__ float Ws[64 * 64];
    __shared__ float xs[64 * 68];
    const float* __restrict__ in  = (const float*)g_agg;
    float* __restrict__       out = to_out ? outp : (float*)g_h;

    int t = threadIdx.x;
    int row0 = blockIdx.x * 64;

    for (int i = t; i < 4096; i += 256) Ws[i] = W[i];
    for (int i = t; i < 4096; i += 256) {
        int r = i >> 6, k = i & 63;
        float v = (row0 + r < n) ? in[(size_t)(row0 + r) * HDIM + k] : 0.0f;
        xs[k * 68 + r] = v;
    }
    __syncthreads();

    int tx = t & 15, ty = t >> 4;
    int c0 = tx * 4, r0 = ty * 4;

    float acc[4][4] = {};
#pragma unroll
    for (int k = 0; k < 64; k++) {
        float4 xv = *(const float4*)&xs[k * 68 + r0];
        float4 wv = *(const float4*)&Ws[k * 64 + c0];
        acc[0][0] = fmaf(xv.x, wv.x, acc[0][0]);
        acc[0][1] = fmaf(xv.x, wv.y, acc[0][1]);
        acc[0][2] = fmaf(xv.x, wv.z, acc[0][2]);
        acc[0][3] = fmaf(xv.x, wv.w, acc[0][3]);
        acc[1][0] = fmaf(xv.y, wv.x, acc[1][0]);
        acc[1][1] = fmaf(xv.y, wv.y, acc[1][1]);
        acc[1][2] = fmaf(xv.y, wv.z, acc[1][2]);
        acc[1][3] = fmaf(xv.y, wv.w, acc[1][3]);
        acc[2][0] = fmaf(xv.z, wv.x, acc[2][0]);
        acc[2][1] = fmaf(xv.z, wv.y, acc[2][1]);
        acc[2][2] = fmaf(xv.z, wv.z, acc[2][2]);
        acc[2][3] = fmaf(xv.z, wv.w, acc[2][3]);
        acc[3][0] = fmaf(xv.w, wv.x, acc[3][0]);
        acc[3][1] = fmaf(xv.w, wv.y, acc[3][1]);
        acc[3][2] = fmaf(xv.w, wv.z, acc[3][2]);
        acc[3][3] = fmaf(xv.w, wv.w, acc[3][3]);
    }

    float4 bv = *(const float4*)&b[c0];
#pragma unroll
    for (int rr = 0; rr < 4; rr++) {
        int r = row0 + r0 + rr;
        if (r < n) {
            float4 o;
            o.x = acc[rr][0] + bv.x;
            o.y = acc[rr][1] + bv.y;
            o.z = acc[rr][2] + bv.z;
            o.w = acc[rr][3] + bv.w;
            if (do_relu) {
                o.x = fmaxf(o.x, 0.0f);
                o.y = fmaxf(o.y, 0.0f);
                o.z = fmaxf(o.z, 0.0f);
                o.w = fmaxf(o.w, 0.0f);
            }
            *(float4*)&out[(size_t)r * HDIM + c0] = o;
        }
    }
}

// ---------------- launch ------------------------------------------------------
extern "C" void kernel_launch(void* const* d_in, const int* in_sizes, int n_in,
                              void* d_out, int out_size) {
    const float* x  = (const float*)d_in[0];
    const void*  ei = d_in[1];
    // d_in[2] = edge_features (unused by GCNConv reference)
    const float* W1 = (const float*)d_in[3];
    const float* b1 = (const float*)d_in[4];
    const float* W2 = (const float*)d_in[5];
    const float* b2 = (const float*)d_in[6];
    const float* W3 = (const float*)d_in[7];
    const float* b3 = (const float*)d_in[8];
    float* outp = (float*)d_out;

    int N = in_sizes[0] / HDIM;
    int E = in_sizes[1] / 2;
    int Ep = E / 2;                      // edge pairs (E is even)

    int nb = (N + 511) / 512;

    // ---- dtype probe + CSR build ----
    k_zero_probe<<<(N + 255) / 256, 256>>>(ei, N);
    k_count<<<(Ep + 255) / 256, 256>>>(ei, E, N);
    k_scan1<<<nb, 512>>>(N);
    k_scan2<<<1, 512>>>(nb);
    k_scan3<<<nb, 512>>>(N);
    k_fill<<<(Ep + 255) / 256, 256>>>(ei, E, N);

    // agg: 64 threads/block = 2 warps -> fine retirement granularity
    int agg_blocks  = (N + 1) / 2;
    int gemm_blocks = (N + 63) / 64;

    // ---- layer 1 ----
    k_agg <<<agg_blocks, 64>>>(x, N, 1);
    k_gemm<<<gemm_blocks, 256>>>(W1, b1, outp, N, 1, 0);

    // ---- layer 2 ----
    k_agg <<<agg_blocks, 64>>>(x, N, 0);
    k_gemm<<<gemm_blocks, 256>>>(W2, b2, outp, N, 1, 0);

    // ---- layer 3 (no relu, direct to d_out) ----
    k_agg <<<agg_blocks, 64>>>(x, N, 0);
    k_gemm<<<gemm_blocks, 256>>>(W3, b3, outp, N, 0, 1);
}

// round 8
// speedup vs baseline: 1.0512x; 1.0512x over previous
#include <cuda_runtime.h>
#include <cuda_bf16.h>
#include <cuda_fp16.h>
#include <math.h>

#define MAXN 100000
#define MAXE 1600000
#define HDIM 64

// ---------------- scratch (static device globals; no allocation) -------------
__device__ int     g_counts [MAXN];
__device__ int     g_offsets[MAXN];
__device__ int     g_cursor [MAXN];
__device__ float   g_dis    [MAXN];
__device__ float2  g_epack  [MAXE];       // .x = __int_as_float(src), .y = norm
__device__ float   g_agg    [MAXN * HDIM];
__device__ float   g_h      [MAXN * HDIM];
__device__ __half2 g_hh     [MAXN * (HDIM / 2)];  // fp16 copy of current features
__device__ int     g_bsum   [512];
__device__ int     g_is64;   // 1 if edge_index buffer is int64, 0 if int32

// ---------------- zero + dtype probe -----------------------------------------
// True int64 indices read as int64 lie in [0, n). An int32 buffer misread as
// int64 packs two indices per word -> values >= 2^32. Deterministic.
__global__ void k_zero_probe(const void* __restrict__ ei_raw, int n) {
    int i = blockIdx.x * blockDim.x + threadIdx.x;
    if (i < n) g_counts[i] = 0;
    if (i == 0) {
        const long long* e64 = (const long long*)ei_raw;
        int ok64 = 1;
        for (int k = 0; k < 8; k++) {
            long long v = e64[k];
            if (v < 0 || v >= (long long)n) ok64 = 0;
        }
        g_is64 = ok64;
    }
}

// ---------------- count in-degrees (vectorized: 2 edges/thread) --------------
__global__ void k_count(const void* __restrict__ ei_raw, int e, int n) {
    int i = blockIdx.x * blockDim.x + threadIdx.x;   // pair index
    if (2 * i >= e) return;
    int d0, d1;
    if (g_is64) {
        const longlong2* p = (const longlong2*)((const long long*)ei_raw + e);
        longlong2 v = __ldg(&p[i]);
        d0 = (int)v.x; d1 = (int)v.y;
    } else {
        const int2* p = (const int2*)((const int*)ei_raw + e);
        int2 v = __ldg(&p[i]);
        d0 = v.x; d1 = v.y;
    }
    if ((unsigned)d0 < (unsigned)n) atomicAdd(&g_counts[d0], 1);
    if ((unsigned)d1 < (unsigned)n) atomicAdd(&g_counts[d1], 1);
}

// Block-level exclusive scan of counts (512/block); also dis = rsqrt(deg+1)
__global__ void k_scan1(int n) {
    __shared__ int s[512];
    int t = threadIdx.x;
    int i = blockIdx.x * 512 + t;
    int v = (i < n) ? g_counts[i] : 0;
    s[t] = v;
    __syncthreads();
#pragma unroll
    for (int off = 1; off < 512; off <<= 1) {
        int tv = (t >= off) ? s[t - off] : 0;
        __syncthreads();
        s[t] += tv;
        __syncthreads();
    }
    if (i < n) {
        g_offsets[i] = s[t] - v;
        g_dis[i]     = rsqrtf((float)(v + 1));
    }
    if (t == 511) g_bsum[blockIdx.x] = s[511];
}

__global__ void k_scan2(int nb) {
    __shared__ int s[512];
    int t = threadIdx.x;
    int v = (t < nb) ? g_bsum[t] : 0;
    s[t] = v;
    __syncthreads();
#pragma unroll
    for (int off = 1; off < 512; off <<= 1) {
        int tv = (t >= off) ? s[t - off] : 0;
        __syncthreads();
        s[t] += tv;
        __syncthreads();
    }
    if (t < nb) g_bsum[t] = s[t] - v;
}

__global__ void k_scan3(int n) {
    int i = blockIdx.x * 512 + threadIdx.x;
    if (i < n) {
        int o = g_offsets[i] + g_bsum[blockIdx.x];
        g_offsets[i] = o;
        g_cursor[i]  = o;
    }
}

// ---------------- fill CSR (vectorized: 2 edges/thread) ----------------------
__global__ void k_fill(const void* __restrict__ ei_raw, int e, int n) {
    int i = blockIdx.x * blockDim.x + threadIdx.x;   // pair index
    if (2 * i >= e) return;
    int s0, s1, d0, d1;
    if (g_is64) {
        const longlong2* ps = (const longlong2*)((const long long*)ei_raw);
        const longlong2* pd = (const longlong2*)((const long long*)ei_raw + e);
        longlong2 vs = __ldg(&ps[i]);
        longlong2 vd = __ldg(&pd[i]);
        s0 = (int)vs.x; s1 = (int)vs.y; d0 = (int)vd.x; d1 = (int)vd.y;
    } else {
        const int2* ps = (const int2*)((const int*)ei_raw);
        const int2* pd = (const int2*)((const int*)ei_raw + e);
        int2 vs = __ldg(&ps[i]);
        int2 vd = __ldg(&pd[i]);
        s0 = vs.x; s1 = vs.y; d0 = vd.x; d1 = vd.y;
    }
    if ((unsigned)s0 < (unsigned)n && (unsigned)d0 < (unsigned)n) {
        int p = atomicAdd(&g_cursor[d0], 1);
        g_epack[p] = make_float2(__int_as_float(s0), g_dis[s0] * g_dis[d0]);
    }
    if ((unsigned)s1 < (unsigned)n && (unsigned)d1 < (unsigned)n) {
        int p = atomicAdd(&g_cursor[d1], 1);
        g_epack[p] = make_float2(__int_as_float(s1), g_dis[s1] * g_dis[d1]);
    }
}

// ---------------- x -> half2 copy (layer-1 gather source) --------------------
__global__ void k_x2h(const float* __restrict__ x, int n32) {
    int i = blockIdx.x * blockDim.x + threadIdx.x;
    if (i < n32) {
        float2 v = ((const float2*)x)[i];
        g_hh[i] = __float22half2_rn(v);
    }
}

// ---------------- aggregation: g_agg = A_norm_with_selfloops * in ------------
// Warp per destination node; lane covers cols {2*lane, 2*lane+1}. Neighbor
// gathers read the fp16 feature copy: 128B/row -> ONE L1 wavefront per gather
// (vs 2 for fp32) and half the L2 sectors. Self-loop term stays fp32 exact.
// Accumulation fp32. Unroll-4 keeps 4 gathers in flight.
__global__ void k_agg(const float* __restrict__ xin, int n, int from_x) {
    int warp = (blockIdx.x * blockDim.x + threadIdx.x) >> 5;
    int lane = threadIdx.x & 31;
    if (warp >= n) return;

    const float2* __restrict__ selfsrc =
        (const float2*)(from_x ? xin : (const float*)g_h);
    const __half2* __restrict__ hin = (const __half2*)g_hh;

    float di    = g_dis[warp];
    float selfc = di * di;

    float2 r = __ldg(&selfsrc[(size_t)warp * 32 + lane]);
    float acc0 = r.x * selfc;
    float acc1 = r.y * selfc;

    int start = g_offsets[warp];
    int cnt   = g_counts[warp];
    int j = 0;
    for (; j + 4 <= cnt; j += 4) {
        float2 m0 = __ldg(&g_epack[start + j]);
        float2 m1 = __ldg(&g_epack[start + j + 1]);
        float2 m2 = __ldg(&g_epack[start + j + 2]);
        float2 m3 = __ldg(&g_epack[start + j + 3]);
        __half2 h0 = __ldg(&hin[(size_t)__float_as_int(m0.x) * 32 + lane]);
        __half2 h1 = __ldg(&hin[(size_t)__float_as_int(m1.x) * 32 + lane]);
        __half2 h2 = __ldg(&hin[(size_t)__float_as_int(m2.x) * 32 + lane]);
        __half2 h3 = __ldg(&hin[(size_t)__float_as_int(m3.x) * 32 + lane]);
        float2 f0 = __half22float2(h0);
        float2 f1 = __half22float2(h1);
        float2 f2 = __half22float2(h2);
        float2 f3 = __half22float2(h3);
        acc0 = fmaf(m0.y, f0.x, acc0);  acc1 = fmaf(m0.y, f0.y, acc1);
        acc0 = fmaf(m1.y, f1.x, acc0);  acc1 = fmaf(m1.y, f1.y, acc1);
        acc0 = fmaf(m2.y, f2.x, acc0);  acc1 = fmaf(m2.y, f2.y, acc1);
        acc0 = fmaf(m3.y, f3.x, acc0);  acc1 = fmaf(m3.y, f3.y, acc1);
    }
    for (; j < cnt; j++) {
        float2 m = __ldg(&g_epack[start + j]);
        __half2 h = __ldg(&hin[(size_t)__float_as_int(m.x) * 32 + lane]);
        float2 f = __half22float2(h);
        acc0 = fmaf(m.y, f.x, acc0);
        acc1 = fmaf(m.y, f.y, acc1);
    }
    ((float2*)g_agg)[(size_t)warp * 32 + lane] = make_float2(acc0, acc1);
}

// ---------------- GEMM: out = [relu](g_agg @ W + b),  g_agg: n x 64 ----------
// Epilogue also writes the fp16 feature copy for the next layer's gathers
// (write_half), so no extra conversion pass is needed between layers.
__global__ void k_gemm(const float* __restrict__ W, const float* __restrict__ b,
                       float* __restrict__ outp, int n, int do_relu, int to_out) {
    __shared__ float Ws[64 * 64];
    __shared__ float xs[64 * 68];
    const float* __restrict__ in  = (const float*)g_agg;
    float* __restrict__       out = to_out ? outp : (float*)g_h;

    int t = threadIdx.x;
    int row0 = blockIdx.x * 64;

    for (int i = t; i < 4096; i += 256) Ws[i] = W[i];
    for (int i = t; i < 4096; i += 256) {
        int r = i >> 6, k = i & 63;
        float v = (row0 + r < n) ? in[(size_t)(row0 + r) * HDIM + k] : 0.0f;
        xs[k * 68 + r] = v;
    }
    __syncthreads();

    int tx = t & 15, ty = t >> 4;
    int c0 = tx * 4, r0 = ty * 4;

    float acc[4][4] = {};
#pragma unroll
    for (int k = 0; k < 64; k++) {
        float4 xv = *(const float4*)&xs[k * 68 + r0];
        float4 wv = *(const float4*)&Ws[k * 64 + c0];
        acc[0][0] = fmaf(xv.x, wv.x, acc[0][0]);
        acc[0][1] = fmaf(xv.x, wv.y, acc[0][1]);
        acc[0][2] = fmaf(xv.x, wv.z, acc[0][2]);
        acc[0][3] = fmaf(xv.x, wv.w, acc[0][3]);
        acc[1][0] = fmaf(xv.y, wv.x, acc[1][0]);
        acc[1][1] = fmaf(xv.y, wv.y, acc[1][1]);
        acc[1][2] = fmaf(xv.y, wv.z, acc[1][2]);
        acc[1][3] = fmaf(xv.y, wv.w, acc[1][3]);
        acc[2][0] = fmaf(xv.z, wv.x, acc[2][0]);
        acc[2][1] = fmaf(xv.z, wv.y, acc[2][1]);
        acc[2][2] = fmaf(xv.z, wv.z, acc[2][2]);
        acc[2][3] = fmaf(xv.z, wv.w, acc[2][3]);
        acc[3][0] = fmaf(xv.w, wv.x, acc[3][0]);
        acc[3][1] = fmaf(xv.w, wv.y, acc[3][1]);
        acc[3][2] = fmaf(xv.w, wv.z, acc[3][2]);
        acc[3][3] = fmaf(xv.w, wv.w, acc[3][3]);
    }

    float4 bv = *(const float4*)&b[c0];
#pragma unroll
    for (int rr = 0; rr < 4; rr++) {
        int r = row0 + r0 + rr;
        if (r < n) {
            float4 o;
            o.x = acc[rr][0] + bv.x;
            o.y = acc[rr][1] + bv.y;
            o.z = acc[rr][2] + bv.z;
            o.w = acc[rr][3] + bv.w;
            if (do_relu) {
                o.x = fmaxf(o.x, 0.0f);
                o.y = fmaxf(o.y, 0.0f);
                o.z = fmaxf(o.z, 0.0f);
                o.w = fmaxf(o.w, 0.0f);
            }
            *(float4*)&out[(size_t)r * HDIM + c0] = o;
            if (!to_out) {                 // fp16 copy for next layer's gathers
                union { __half2 h[2]; uint2 u; } cv;
                cv.h[0] = __float22half2_rn(make_float2(o.x, o.y));
                cv.h[1] = __float22half2_rn(make_float2(o.z, o.w));
                *(uint2*)&g_hh[(size_t)r * 32 + (c0 >> 1)] = cv.u;
            }
        }
    }
}

// ---------------- launch ------------------------------------------------------
extern "C" void kernel_launch(void* const* d_in, const int* in_sizes, int n_in,
                              void* d_out, int out_size) {
    const float* x  = (const float*)d_in[0];
    const void*  ei = d_in[1];
    // d_in[2] = edge_features (unused by GCNConv reference)
    const float* W1 = (const float*)d_in[3];
    const float* b1 = (const float*)d_in[4];
    const float* W2 = (const float*)d_in[5];
    const float* b2 = (const float*)d_in[6];
    const float* W3 = (const float*)d_in[7];
    const float* b3 = (const float*)d_in[8];
    float* outp = (float*)d_out;

    int N = in_sizes[0] / HDIM;
    int E = in_sizes[1] / 2;
    int Ep = E / 2;                      // edge pairs (E is even)

    int nb = (N + 511) / 512;

    // ---- dtype probe + CSR build + fp16 copy of x ----
    k_zero_probe<<<(N + 255) / 256, 256>>>(ei, N);
    k_count<<<(Ep + 255) / 256, 256>>>(ei, E, N);
    k_scan1<<<nb, 512>>>(N);
    k_scan2<<<1, 512>>>(nb);
    k_scan3<<<nb, 512>>>(N);
    k_fill<<<(Ep + 255) / 256, 256>>>(ei, E, N);
    k_x2h<<<(N * 32 + 255) / 256, 256>>>(x, N * 32);

    int agg_blocks  = (N * 32 + 255) / 256;
    int gemm_blocks = (N + 63) / 64;

    // ---- layer 1 ----
    k_agg <<<agg_blocks, 256>>>(x, N, 1);
    k_gemm<<<gemm_blocks, 256>>>(W1, b1, outp, N, 1, 0);

    // ---- layer 2 ----
    k_agg <<<agg_blocks, 256>>>(x, N, 0);
    k_gemm<<<gemm_blocks, 256>>>(W2, b2, outp, N, 1, 0);

    // ---- layer 3 (no relu, direct to d_out) ----
    k_agg <<<agg_blocks, 256>>>(x, N, 0);
    k_gemm<<<gemm_blocks, 256>>>(W3, b3, outp, N, 0, 1);
}

// round 11
// speedup vs baseline: 1.0863x; 1.0334x over previous
#include <cuda_runtime.h>
#include <cuda_bf16.h>
#include <cuda_fp16.h>
#include <math.h>

#define MAXN 100000
#define MAXE 1600000
#define HDIM 64

// ---------------- scratch (static device globals; no allocation) -------------
__device__ int     g_counts [MAXN];
__device__ int     g_offsets[MAXN];
__device__ int     g_cursor [MAXN];
__device__ float   g_dis    [MAXN];
__device__ float2  g_epack  [MAXE];       // .x = __int_as_float(src), .y = norm
__device__ float   g_h  [2][MAXN * HDIM];         // fp32 features, ping-pong
__device__ __half2 g_hh [2][MAXN * (HDIM / 2)];   // fp16 features, ping-pong
__device__ int     g_bsum   [512];
__device__ int     g_is64;   // 1 if edge_index buffer is int64, 0 if int32

// ---------------- zero + dtype probe + x->fp16 copy (into hh[0]) -------------
// Grid covers N*32 half2 elements; first N threads also zero counts; thread 0
// runs the dtype probe. True int64 indices read as int64 lie in [0, n); an
// int32 buffer misread as int64 packs two -> values >= 2^32. Deterministic.
__global__ void k_zero_probe_x2h(const void* __restrict__ ei_raw,
                                 const float* __restrict__ x, int n) {
    int i = blockIdx.x * blockDim.x + threadIdx.x;
    int n32 = n * 32;
    if (i < n32) {
        float2 v = ((const float2*)x)[i];
        g_hh[0][i] = __float22half2_rn(v);
    }
    if (i < n) g_counts[i] = 0;
    if (i == 0) {
        const long long* e64 = (const long long*)ei_raw;
        int ok64 = 1;
        for (int k = 0; k < 8; k++) {
            long long v = e64[k];
            if (v < 0 || v >= (long long)n) ok64 = 0;
        }
        g_is64 = ok64;
    }
}

// ---------------- count in-degrees (vectorized: 2 edges/thread) --------------
__global__ void k_count(const void* __restrict__ ei_raw, int e, int n) {
    int i = blockIdx.x * blockDim.x + threadIdx.x;   // pair index
    if (2 * i >= e) return;
    int d0, d1;
    if (g_is64) {
        const longlong2* p = (const longlong2*)((const long long*)ei_raw + e);
        longlong2 v = __ldg(&p[i]);
        d0 = (int)v.x; d1 = (int)v.y;
    } else {
        const int2* p = (const int2*)((const int*)ei_raw + e);
        int2 v = __ldg(&p[i]);
        d0 = v.x; d1 = v.y;
    }
    if ((unsigned)d0 < (unsigned)n) atomicAdd(&g_counts[d0], 1);
    if ((unsigned)d1 < (unsigned)n) atomicAdd(&g_counts[d1], 1);
}

// Block-level exclusive scan of counts (512/block); also dis = rsqrt(deg+1)
__global__ void k_scan1(int n) {
    __shared__ int s[512];
    int t = threadIdx.x;
    int i = blockIdx.x * 512 + t;
    int v = (i < n) ? g_counts[i] : 0;
    s[t] = v;
    __syncthreads();
#pragma unroll
    for (int off = 1; off < 512; off <<= 1) {
        int tv = (t >= off) ? s[t - off] : 0;
        __syncthreads();
        s[t] += tv;
        __syncthreads();
    }
    if (i < n) {
        g_offsets[i] = s[t] - v;
        g_dis[i]     = rsqrtf((float)(v + 1));
    }
    if (t == 511) g_bsum[blockIdx.x] = s[511];
}

__global__ void k_scan2(int nb) {
    __shared__ int s[512];
    int t = threadIdx.x;
    int v = (t < nb) ? g_bsum[t] : 0;
    s[t] = v;
    __syncthreads();
#pragma unroll
    for (int off = 1; off < 512; off <<= 1) {
        int tv = (t >= off) ? s[t - off] : 0;
        __syncthreads();
        s[t] += tv;
        __syncthreads();
    }
    if (t < nb) g_bsum[t] = s[t] - v;
}

__global__ void k_scan3(int n) {
    int i = blockIdx.x * 512 + threadIdx.x;
    if (i < n) {
        int o = g_offsets[i] + g_bsum[blockIdx.x];
        g_offsets[i] = o;
        g_cursor[i]  = o;
    }
}

// ---------------- fill CSR (vectorized: 2 edges/thread) ----------------------
__global__ void k_fill(const void* __restrict__ ei_raw, int e, int n) {
    int i = blockIdx.x * blockDim.x + threadIdx.x;   // pair index
    if (2 * i >= e) return;
    int s0, s1, d0, d1;
    if (g_is64) {
        const longlong2* ps = (const longlong2*)((const long long*)ei_raw);
        const longlong2* pd = (const longlong2*)((const long long*)ei_raw + e);
        longlong2 vs = __ldg(&ps[i]);
        longlong2 vd = __ldg(&pd[i]);
        s0 = (int)vs.x; s1 = (int)vs.y; d0 = (int)vd.x; d1 = (int)vd.y;
    } else {
        const int2* ps = (const int2*)((const int*)ei_raw);
        const int2* pd = (const int2*)((const int*)ei_raw + e);
        int2 vs = __ldg(&ps[i]);
        int2 vd = __ldg(&pd[i]);
        s0 = vs.x; s1 = vs.y; d0 = vd.x; d1 = vd.y;
    }
    if ((unsigned)s0 < (unsigned)n && (unsigned)d0 < (unsigned)n) {
        int p = atomicAdd(&g_cursor[d0], 1);
        g_epack[p] = make_float2(__int_as_float(s0), g_dis[s0] * g_dis[d0]);
    }
    if ((unsigned)s1 < (unsigned)n && (unsigned)d1 < (unsigned)n) {
        int p = atomicAdd(&g_cursor[d1], 1);
        g_epack[p] = make_float2(__int_as_float(s1), g_dis[s1] * g_dis[d1]);
    }
}

// ---------------- fused layer: out = [relu]( (A_hat @ in) @ W + b ) ----------
// One block = 64 dst nodes, 256 threads. PING-PONG buffers: the read set
// (h[h_in] or x, hh[hh_in]) and write set (h[h_out], hh[hh_out] or d_out) are
// disjoint in every launch -> no cross-block read/write race (the R10 bug).
// Phase 1 (aggregate): warp w handles 8 nodes sequentially; lane covers cols
//   {2l,2l+1}; neighbor gathers read fp16 (128B/row); fp32 accumulation;
//   results go straight into the transposed smem tile.
// Phase 2 (GEMM): 4x4 register micro-tile. Epilogue: fp32 (+ fp16 copy).
__global__ void k_layer(const float* __restrict__ xin,
                        const float* __restrict__ W, const float* __restrict__ b,
                        float* __restrict__ outp,
                        int n, int do_relu, int to_out, int from_x,
                        int h_in, int hh_in, int h_out, int hh_out) {
    __shared__ float Ws[64 * 64];
    __shared__ float xs[64 * 68];   // transposed tile: xs[k*68 + r]

    const int t    = threadIdx.x;
    const int wid  = t >> 5;
    const int lane = t & 31;
    const int row0 = blockIdx.x * 64;

    for (int i = t; i < 4096; i += 256) Ws[i] = W[i];

    const float2* __restrict__ selfsrc =
        (const float2*)(from_x ? xin : (const float*)g_h[h_in]);
    const __half2* __restrict__ hin = (const __half2*)g_hh[hh_in];

    // ---- phase 1: aggregate 8 nodes per warp ----
#pragma unroll 1
    for (int rr = 0; rr < 8; rr++) {
        const int r    = wid * 8 + rr;     // local row
        const int node = row0 + r;
        float acc0 = 0.f, acc1 = 0.f;
        if (node < n) {
            float di    = g_dis[node];
            float selfc = di * di;
            float2 sv = __ldg(&selfsrc[(size_t)node * 32 + lane]);
            acc0 = sv.x * selfc;
            acc1 = sv.y * selfc;

            int start = g_offsets[node];
            int cnt   = g_counts[node];
            int j = 0;
            for (; j + 4 <= cnt; j += 4) {
                float2 m0 = __ldg(&g_epack[start + j]);
                float2 m1 = __ldg(&g_epack[start + j + 1]);
                float2 m2 = __ldg(&g_epack[start + j + 2]);
                float2 m3 = __ldg(&g_epack[start + j + 3]);
                __half2 h0 = __ldg(&hin[(size_t)__float_as_int(m0.x) * 32 + lane]);
                __half2 h1 = __ldg(&hin[(size_t)__float_as_int(m1.x) * 32 + lane]);
                __half2 h2 = __ldg(&hin[(size_t)__float_as_int(m2.x) * 32 + lane]);
                __half2 h3 = __ldg(&hin[(size_t)__float_as_int(m3.x) * 32 + lane]);
                float2 f0 = __half22float2(h0);
                float2 f1 = __half22float2(h1);
                float2 f2 = __half22float2(h2);
                float2 f3 = __half22float2(h3);
                acc0 = fmaf(m0.y, f0.x, acc0);  acc1 = fmaf(m0.y, f0.y, acc1);
                acc0 = fmaf(m1.y, f1.x, acc0);  acc1 = fmaf(m1.y, f1.y, acc1);
                acc0 = fmaf(m2.y, f2.x, acc0);  acc1 = fmaf(m2.y, f2.y, acc1);
                acc0 = fmaf(m3.y, f3.x, acc0);  acc1 = fmaf(m3.y, f3.y, acc1);
            }
            for (; j < cnt; j++) {
                float2 m = __ldg(&g_epack[start + j]);
                __half2 h = __ldg(&hin[(size_t)__float_as_int(m.x) * 32 + lane]);
                float2 f = __half22float2(h);
                acc0 = fmaf(m.y, f.x, acc0);
                acc1 = fmaf(m.y, f.y, acc1);
            }
        }
        xs[(2 * lane)     * 68 + r] = acc0;
        xs[(2 * lane + 1) * 68 + r] = acc1;
    }
    __syncthreads();

    // ---- phase 2: GEMM 64x64 ----
    float* __restrict__ out = to_out ? outp : (float*)g_h[h_out];
    const int tx = t & 15, ty = t >> 4;
    const int c0 = tx * 4, r0 = ty * 4;

    float acc[4][4] = {};
#pragma unroll
    for (int k = 0; k < 64; k++) {
        float4 xv = *(const float4*)&xs[k * 68 + r0];
        float4 wv = *(const float4*)&Ws[k * 64 + c0];
        acc[0][0] = fmaf(xv.x, wv.x, acc[0][0]);
        acc[0][1] = fmaf(xv.x, wv.y, acc[0][1]);
        acc[0][2] = fmaf(xv.x, wv.z, acc[0][2]);
        acc[0][3] = fmaf(xv.x, wv.w, acc[0][3]);
        acc[1][0] = fmaf(xv.y, wv.x, acc[1][0]);
        acc[1][1] = fmaf(xv.y, wv.y, acc[1][1]);
        acc[1][2] = fmaf(xv.y, wv.z, acc[1][2]);
        acc[1][3] = fmaf(xv.y, wv.w, acc[1][3]);
        acc[2][0] = fmaf(xv.z, wv.x, acc[2][0]);
        acc[2][1] = fmaf(xv.z, wv.y, acc[2][1]);
        acc[2][2] = fmaf(xv.z, wv.z, acc[2][2]);
        acc[2][3] = fmaf(xv.z, wv.w, acc[2][3]);
        acc[3][0] = fmaf(xv.w, wv.x, acc[3][0]);
        acc[3][1] = fmaf(xv.w, wv.y, acc[3][1]);
        acc[3][2] = fmaf(xv.w, wv.z, acc[3][2]);
        acc[3][3] = fmaf(xv.w, wv.w, acc[3][3]);
    }

    float4 bv = *(const float4*)&b[c0];
#pragma unroll
    for (int rr = 0; rr < 4; rr++) {
        int r = row0 + r0 + rr;
        if (r < n) {
            float4 o;
            o.x = acc[rr][0] + bv.x;
            o.y = acc[rr][1] + bv.y;
            o.z = acc[rr][2] + bv.z;
            o.w = acc[rr][3] + bv.w;
            if (do_relu) {
                o.x = fmaxf(o.x, 0.0f);
                o.y = fmaxf(o.y, 0.0f);
                o.z = fmaxf(o.z, 0.0f);
                o.w = fmaxf(o.w, 0.0f);
            }
            *(float4*)&out[(size_t)r * HDIM + c0] = o;
            if (!to_out) {                 // fp16 copy for next layer's gathers
                union { __half2 h[2]; uint2 u; } cv;
                cv.h[0] = __float22half2_rn(make_float2(o.x, o.y));
                cv.h[1] = __float22half2_rn(make_float2(o.z, o.w));
                *(uint2*)&g_hh[hh_out][(size_t)r * 32 + (c0 >> 1)] = cv.u;
            }
        }
    }
}

// ---------------- launch ------------------------------------------------------
extern "C" void kernel_launch(void* const* d_in, const int* in_sizes, int n_in,
                              void* d_out, int out_size) {
    const float* x  = (const float*)d_in[0];
    const void*  ei = d_in[1];
    // d_in[2] = edge_features (unused by GCNConv reference)
    const float* W1 = (const float*)d_in[3];
    const float* b1 = (const float*)d_in[4];
    const float* W2 = (const float*)d_in[5];
    const float* b2 = (const float*)d_in[6];
    const float* W3 = (const float*)d_in[7];
    const float* b3 = (const float*)d_in[8];
    float* outp = (float*)d_out;

    int N = in_sizes[0] / HDIM;
    int E = in_sizes[1] / 2;
    int Ep = E / 2;                      // edge pairs (E is even)

    int nb = (N + 511) / 512;

    // ---- dtype probe + zero + fp16(x)->hh[0] + CSR build ----
    k_zero_probe_x2h<<<(N * 32 + 255) / 256, 256>>>(ei, x, N);
    k_count<<<(Ep + 255) / 256, 256>>>(ei, E, N);
    k_scan1<<<nb, 512>>>(N);
    k_scan2<<<1, 512>>>(nb);
    k_scan3<<<nb, 512>>>(N);
    k_fill<<<(Ep + 255) / 256, 256>>>(ei, E, N);

    int layer_blocks = (N + 63) / 64;

    // ---- fused layers, ping-pong buffers (read/write sets disjoint) ----
    // L1: self=x,      gather hh[0] -> h[0], hh[1]
    // L2: self=h[0],   gather hh[1] -> h[1], hh[0]
    // L3: self=h[1],   gather hh[0] -> d_out
    k_layer<<<layer_blocks, 256>>>(x, W1, b1, outp, N, 1, 0, 1, 0, 0, 0, 1);
    k_layer<<<layer_blocks, 256>>>(x, W2, b2, outp, N, 1, 0, 0, 0, 1, 1, 0);
    k_layer<<<layer_blocks, 256>>>(x, W3, b3, outp, N, 0, 1, 0, 1, 0, 0, 0);
}